// round 1
// baseline (speedup 1.0000x reference)
#include <cuda_runtime.h>
#include <math.h>

// ---------------------------------------------------------------------------
// Problem constants
//   x      : [B=4, N=2048, D=1024] f32
//   W_qkv  : [1024, 3072] f32   (cols: s*1024 + h*64 + e, s=0:Q 1:K 2:V)
//   W_o    : [1024, 1024] f32
//   out    : [4, 2048, 1024] f32
// ---------------------------------------------------------------------------
#define BB 4
#define NN 2048
#define DD 1024
#define HH 16
#define EE 64
#define MTOT (BB * NN)          // 8192

// Scratch buffers (module globals; no runtime allocation)
__device__ float g_qkv[MTOT * 3 * DD];   // [8192, 3072]
__device__ float g_attn[MTOT * DD];      // [8192, 1024]

// ---------------------------------------------------------------------------
// SGEMM: C[M,N] = A[M,K] @ B[K,N], all row-major, fp32.
// 128x128 tile, BK=8, 256 threads, 8x8 per thread.
// Requires: M%128==0, N%128==0, K%8==0, N%4==0, K%4==0.
// ---------------------------------------------------------------------------
__global__ __launch_bounds__(256, 2)
void sgemm128(const float* __restrict__ A, const float* __restrict__ B,
              float* __restrict__ C, int M, int N, int K) {
    __shared__ float As[8][128];
    __shared__ float Bs[8][128];

    const int tid = threadIdx.x;
    const int bx = blockIdx.x, by = blockIdx.y;

    const int arow = tid >> 1;           // 0..127
    const int acol = (tid & 1) << 2;     // 0 or 4
    const int brow = tid >> 5;           // 0..7
    const int bcol = (tid & 31) << 2;    // 0..124

    const float* Aptr = A + (size_t)(by * 128 + arow) * K + acol;
    const float* Bptr = B + (size_t)brow * N + bx * 128 + bcol;

    const int ty = tid >> 4;             // 0..15
    const int tx = tid & 15;             // 0..15

    float acc[8][8];
#pragma unroll
    for (int i = 0; i < 8; i++)
#pragma unroll
        for (int j = 0; j < 8; j++) acc[i][j] = 0.0f;

    for (int k0 = 0; k0 < K; k0 += 8) {
        float4 av = *(const float4*)(Aptr + k0);
        As[acol + 0][arow] = av.x;
        As[acol + 1][arow] = av.y;
        As[acol + 2][arow] = av.z;
        As[acol + 3][arow] = av.w;
        *(float4*)&Bs[brow][bcol] = *(const float4*)(Bptr + (size_t)k0 * N);
        __syncthreads();

#pragma unroll
        for (int kk = 0; kk < 8; kk++) {
            float a[8], b[8];
            *(float4*)(a)     = *(const float4*)&As[kk][ty * 8];
            *(float4*)(a + 4) = *(const float4*)&As[kk][ty * 8 + 4];
            *(float4*)(b)     = *(const float4*)&Bs[kk][tx * 8];
            *(float4*)(b + 4) = *(const float4*)&Bs[kk][tx * 8 + 4];
#pragma unroll
            for (int i = 0; i < 8; i++)
#pragma unroll
                for (int j = 0; j < 8; j++)
                    acc[i][j] = fmaf(a[i], b[j], acc[i][j]);
        }
        __syncthreads();
    }

#pragma unroll
    for (int i = 0; i < 8; i++) {
        float* Crow = C + (size_t)(by * 128 + ty * 8 + i) * N + bx * 128 + tx * 8;
        float4 c0 = make_float4(acc[i][0], acc[i][1], acc[i][2], acc[i][3]);
        float4 c1 = make_float4(acc[i][4], acc[i][5], acc[i][6], acc[i][7]);
        *(float4*)(Crow)     = c0;
        *(float4*)(Crow + 4) = c1;
    }
}

// ---------------------------------------------------------------------------
// Attention (anti-causal, softmax over j axis):
//   S[i,j] = dot(K_i, Q_j) / 8, valid for j >= i
//   out[i,e] = sum_j softmax_j(S[i,:]) * V[j,e]
// One CTA per (b,h, 64-row i-tile). Streams j tiles from the diagonal to N.
// 256 threads = 16x16, each owns a 4x4 fragment.
// ---------------------------------------------------------------------------
#define TILE 64
#define PAD  (TILE + 1)
#define SMEM_ATTN (4 * TILE * PAD * (int)sizeof(float))

__device__ __forceinline__ float rowmax16(float v) {
#pragma unroll
    for (int o = 8; o > 0; o >>= 1)
        v = fmaxf(v, __shfl_xor_sync(0xffffffffu, v, o, 16));
    return v;
}
__device__ __forceinline__ float rowsum16(float v) {
#pragma unroll
    for (int o = 8; o > 0; o >>= 1)
        v += __shfl_xor_sync(0xffffffffu, v, o, 16);
    return v;
}

__global__ __launch_bounds__(256, 3)
void attn_kernel(const float* __restrict__ qkv, float* __restrict__ outp) {
    extern __shared__ float sm[];
    float* Kt = sm;                    // [64][65]
    float* Qt = Kt + TILE * PAD;       // [64][65]
    float* Vt = Qt + TILE * PAD;       // [64][65]
    float* Pt = Vt + TILE * PAD;       // [64][65]

    const int bh = blockIdx.y;
    const int b  = bh >> 4;
    const int h  = bh & 15;
    const int i0 = blockIdx.x * TILE;

    const int tid = threadIdx.x;
    const int ty  = tid >> 4;          // row group
    const int tx  = tid & 15;          // col group

    // Load K tile: K[b,h,i0+r,e] = qkv[(b*N + i0+r)*3072 + 1024 + h*64 + e]
    {
        for (int idx = tid; idx < TILE * 16; idx += 256) {
            int r = idx >> 4;
            int c = (idx & 15) << 2;
            const float* src = qkv + ((size_t)(b * NN + i0 + r) * 3 * DD) + DD + h * EE + c;
            float4 v = *(const float4*)src;
            float* dst = &Kt[r * PAD + c];
            dst[0] = v.x; dst[1] = v.y; dst[2] = v.z; dst[3] = v.w;
        }
    }

    float m[4], l[4], O[4][4];
#pragma unroll
    for (int r = 0; r < 4; r++) {
        m[r] = -INFINITY; l[r] = 0.0f;
#pragma unroll
        for (int c = 0; c < 4; c++) O[r][c] = 0.0f;
    }

    const int jt0 = i0 / TILE;
    const int nTiles = NN / TILE;

    for (int jt = jt0; jt < nTiles; jt++) {
        const int j0 = jt * TILE;
        // Load Q tile (s=0) and V tile (s=2), rows j0..j0+63
        for (int idx = tid; idx < TILE * 16; idx += 256) {
            int r = idx >> 4;
            int c = (idx & 15) << 2;
            const float* base = qkv + ((size_t)(b * NN + j0 + r) * 3 * DD) + h * EE + c;
            float4 qv = *(const float4*)(base);
            float4 vv = *(const float4*)(base + 2 * DD);
            float* qdst = &Qt[r * PAD + c];
            float* vdst = &Vt[r * PAD + c];
            qdst[0] = qv.x; qdst[1] = qv.y; qdst[2] = qv.z; qdst[3] = qv.w;
            vdst[0] = vv.x; vdst[1] = vv.y; vdst[2] = vv.z; vdst[3] = vv.w;
        }
        __syncthreads();

        // S[4][4] = K_i . Q_j
        float S[4][4];
#pragma unroll
        for (int r = 0; r < 4; r++)
#pragma unroll
            for (int c = 0; c < 4; c++) S[r][c] = 0.0f;

#pragma unroll 8
        for (int e = 0; e < EE; e++) {
            float kf[4], qf[4];
#pragma unroll
            for (int r = 0; r < 4; r++) kf[r] = Kt[(ty * 4 + r) * PAD + e];
#pragma unroll
            for (int c = 0; c < 4; c++) qf[c] = Qt[(tx * 4 + c) * PAD + e];
#pragma unroll
            for (int r = 0; r < 4; r++)
#pragma unroll
                for (int c = 0; c < 4; c++)
                    S[r][c] = fmaf(kf[r], qf[c], S[r][c]);
        }

        // scale + mask (only the diagonal tile has masked entries)
        const bool diag = (j0 == i0);
#pragma unroll
        for (int r = 0; r < 4; r++) {
            int gi = i0 + ty * 4 + r;
#pragma unroll
            for (int c = 0; c < 4; c++) {
                int gj = j0 + tx * 4 + c;
                float sv = S[r][c] * 0.125f;
                if (diag && gj < gi) sv = -INFINITY;
                S[r][c] = sv;
            }
        }

        // online softmax update
        float scale[4];
#pragma unroll
        for (int r = 0; r < 4; r++) {
            float tmax = fmaxf(fmaxf(S[r][0], S[r][1]), fmaxf(S[r][2], S[r][3]));
            tmax = rowmax16(tmax);
            float mnew = fmaxf(m[r], tmax);
            scale[r] = __expf(m[r] - mnew);
            m[r] = mnew;
            float rs = 0.0f;
#pragma unroll
            for (int c = 0; c < 4; c++) {
                float p = __expf(S[r][c] - mnew);
                S[r][c] = p;
                rs += p;
            }
            rs = rowsum16(rs);
            l[r] = l[r] * scale[r] + rs;
#pragma unroll
            for (int c = 0; c < 4; c++) O[r][c] *= scale[r];
        }

        // write P to smem
#pragma unroll
        for (int r = 0; r < 4; r++)
#pragma unroll
            for (int c = 0; c < 4; c++)
                Pt[(ty * 4 + r) * PAD + (tx * 4 + c)] = S[r][c];
        __syncthreads();

        // O[r][e] += sum_j P[r][j] * V[j][e]   (e block = tx*4)
#pragma unroll 8
        for (int j = 0; j < TILE; j++) {
            float vf[4];
#pragma unroll
            for (int c = 0; c < 4; c++) vf[c] = Vt[j * PAD + tx * 4 + c];
#pragma unroll
            for (int r = 0; r < 4; r++) {
                float p = Pt[(ty * 4 + r) * PAD + j];
#pragma unroll
                for (int c = 0; c < 4; c++)
                    O[r][c] = fmaf(p, vf[c], O[r][c]);
            }
        }
        __syncthreads();
    }

    // normalize and store: attn_out[(b*N + i)*D + h*64 + e]
#pragma unroll
    for (int r = 0; r < 4; r++) {
        float inv = 1.0f / l[r];
        int gi = i0 + ty * 4 + r;
        float* dst = outp + (size_t)(b * NN + gi) * DD + h * EE + tx * 4;
        float4 v = make_float4(O[r][0] * inv, O[r][1] * inv, O[r][2] * inv, O[r][3] * inv);
        *(float4*)dst = v;
    }
}

// ---------------------------------------------------------------------------
extern "C" void kernel_launch(void* const* d_in, const int* in_sizes, int n_in,
                              void* d_out, int out_size) {
    const float* x     = (const float*)d_in[0];
    const float* Wqkv  = (const float*)d_in[1];
    const float* Wo    = (const float*)d_in[2];
    float* out = (float*)d_out;

    float* qkv  = nullptr;
    float* attn = nullptr;
    cudaGetSymbolAddress((void**)&qkv,  g_qkv);
    cudaGetSymbolAddress((void**)&attn, g_attn);

    cudaFuncSetAttribute(attn_kernel, cudaFuncAttributeMaxDynamicSharedMemorySize, SMEM_ATTN);

    // 1) QKV projection: [8192,1024] @ [1024,3072] -> g_qkv
    sgemm128<<<dim3(3 * DD / 128, MTOT / 128), 256>>>(x, Wqkv, qkv, MTOT, 3 * DD, DD);

    // 2) attention -> g_attn [8192,1024]
    attn_kernel<<<dim3(NN / TILE, BB * HH), 256, SMEM_ATTN>>>(qkv, attn);

    // 3) output projection: [8192,1024] @ [1024,1024] -> out
    sgemm128<<<dim3(DD / 128, MTOT / 128), 256>>>(attn, Wo, out, MTOT, DD, DD);
}

// round 3
// speedup vs baseline: 1.4101x; 1.4101x over previous
#include <cuda_runtime.h>
#include <cuda_bf16.h>
#include <cstdint>
#include <math.h>

// ---------------------------------------------------------------------------
// Problem: x[4,2048,1024] f32; W_qkv[1024,3072]; W_o[1024,1024]; out[4,2048,1024]
//   1) split x -> A' bf16 [8192, 3072]  (hi | lo | hi along K)
//   2) split/transpose W_qkv -> B' bf16 [3072, 3072] (hi ; hi ; lo)
//   3) HMMA bf16 GEMM -> g_qkv f32 [8192, 3072]
//   4) flash-style anti-causal attention (fp32 SIMT) -> g_attn
//   5) split g_attn -> A' ; split/transpose W_o -> B'[1024,3072]
//   6) HMMA bf16 GEMM -> out
// ---------------------------------------------------------------------------
#define BB 4
#define NN 2048
#define DD 1024
#define HH 16
#define EE 64
#define MTOT (BB * NN)   // 8192
#define KP   3072
#define SA   40          // smem row stride in bf16 (32 data + 8 pad)
#define NSTAGE 96        // KP / 32

__device__ float         g_qkv[MTOT * 3 * DD];
__device__ float         g_attn[MTOT * DD];
__device__ __nv_bfloat16 g_A[MTOT * KP];
__device__ __nv_bfloat16 g_B[3 * DD * KP];

// ===========================================================================
__device__ __forceinline__ uint32_t smem_u32(const void* p) {
    uint32_t a;
    asm("{ .reg .u64 t; cvta.to.shared.u64 t, %1; cvt.u32.u64 %0, t; }"
        : "=r"(a) : "l"(p));
    return a;
}
__device__ __forceinline__ void cp_async16(uint32_t dst, const void* src) {
    asm volatile("cp.async.cg.shared.global [%0], [%1], 16;"
                 :: "r"(dst), "l"(src) : "memory");
}
__device__ __forceinline__ void ldsm_x4(uint32_t* r, uint32_t addr) {
    asm volatile("ldmatrix.sync.aligned.m8n8.x4.shared.b16 {%0,%1,%2,%3}, [%4];"
                 : "=r"(r[0]), "=r"(r[1]), "=r"(r[2]), "=r"(r[3]) : "r"(addr));
}
__device__ __forceinline__ void mma_bf16(float* d, const uint32_t* a, const uint32_t* b) {
    asm volatile(
        "mma.sync.aligned.m16n8k16.row.col.f32.bf16.bf16.f32 "
        "{%0,%1,%2,%3}, {%4,%5,%6,%7}, {%8,%9}, {%0,%1,%2,%3};"
        : "+f"(d[0]), "+f"(d[1]), "+f"(d[2]), "+f"(d[3])
        : "r"(a[0]), "r"(a[1]), "r"(a[2]), "r"(a[3]), "r"(b[0]), "r"(b[1]));
}

// ===========================================================================
// HMMA GEMM: C[M,Nn] f32 = A[M,KP] bf16 @ B[Nn,KP]^T bf16
// 128x128 CTA tile, 8 warps of 64x32, BK=32, triple-buffered cp.async.
// ===========================================================================
#define BUFB (128 * SA * 2)                 // bytes per matrix per stage
#define SMEM_GEMM (3 * 2 * BUFB)            // 61440

__global__ __launch_bounds__(256, 2)
void gemm_hmma(const __nv_bfloat16* __restrict__ A,
               const __nv_bfloat16* __restrict__ B,
               float* __restrict__ C, int M, int Nn) {
    extern __shared__ __nv_bfloat16 smbf[];
    const int tid  = threadIdx.x;
    const int wid  = tid >> 5;
    const int lane = tid & 31;
    const int m0 = blockIdx.y * 128;
    const int n0 = blockIdx.x * 128;
    const int wm = (wid >> 2) * 64;   // warp row offset
    const int wn = (wid & 3) * 32;    // warp col offset

    const uint32_t sbase = smem_u32(smbf);
    const uint32_t aoff0 = sbase;
    const uint32_t boff0 = sbase + 3 * BUFB;

    const __nv_bfloat16* Ag = A + (size_t)m0 * KP;
    const __nv_bfloat16* Bg = B + (size_t)n0 * KP;

    // global->smem mapping: thread -> row tid/2, two 16B chunks
    const int lr  = tid >> 1;
    const int lkc = (tid & 1) * 2;

    auto load_stage = [&](int s) {
        const int buf = s % 3;
        const uint32_t ab = aoff0 + buf * BUFB;
        const uint32_t bb = boff0 + buf * BUFB;
        const int k0 = s * 32;
#pragma unroll
        for (int j = 0; j < 2; j++) {
            const int kc = lkc + j;
            const uint32_t doff = (uint32_t)(lr * SA + kc * 8) * 2;
            cp_async16(ab + doff, Ag + (size_t)lr * KP + k0 + kc * 8);
            cp_async16(bb + doff, Bg + (size_t)lr * KP + k0 + kc * 8);
        }
        asm volatile("cp.async.commit_group;" ::: "memory");
    };

    float acc[4][4][4];
#pragma unroll
    for (int i = 0; i < 4; i++)
#pragma unroll
        for (int j = 0; j < 4; j++)
#pragma unroll
            for (int k = 0; k < 4; k++) acc[i][j][k] = 0.0f;

    // ldmatrix per-lane address components
    const int arow  = wm + (lane & 15);
    const int akoff = (lane >> 4) * 8;
    const int brow  = wn + (lane >> 4) * 8 + (lane & 7);
    const int bkoff = ((lane >> 3) & 1) * 8;

    load_stage(0);
    load_stage(1);

    for (int s = 0; s < NSTAGE; s++) {
        if (s + 1 < NSTAGE)
            asm volatile("cp.async.wait_group 1;" ::: "memory");
        else
            asm volatile("cp.async.wait_group 0;" ::: "memory");
        __syncthreads();
        if (s + 2 < NSTAGE) load_stage(s + 2);

        const int buf = s % 3;
        const uint32_t ab = aoff0 + buf * BUFB;
        const uint32_t bb = boff0 + buf * BUFB;

#pragma unroll
        for (int ksub = 0; ksub < 2; ksub++) {
            uint32_t af[4][4], bf[2][4];
#pragma unroll
            for (int mt = 0; mt < 4; mt++)
                ldsm_x4(af[mt], ab + (uint32_t)((arow + mt * 16) * SA + ksub * 16 + akoff) * 2);
#pragma unroll
            for (int p = 0; p < 2; p++)
                ldsm_x4(bf[p], bb + (uint32_t)((brow + p * 16) * SA + ksub * 16 + bkoff) * 2);
#pragma unroll
            for (int mt = 0; mt < 4; mt++) {
#pragma unroll
                for (int nt = 0; nt < 4; nt++)
                    mma_bf16(acc[mt][nt], af[mt], &bf[nt >> 1][(nt & 1) * 2]);
            }
        }
    }

    // epilogue: direct float2 stores
    const int grp = lane >> 2;
    const int tig = lane & 3;
#pragma unroll
    for (int mt = 0; mt < 4; mt++) {
#pragma unroll
        for (int nt = 0; nt < 4; nt++) {
            const int row = m0 + wm + mt * 16 + grp;
            const int col = n0 + wn + nt * 8 + tig * 2;
            float2 v0 = make_float2(acc[mt][nt][0], acc[mt][nt][1]);
            float2 v1 = make_float2(acc[mt][nt][2], acc[mt][nt][3]);
            *(float2*)&C[(size_t)row * Nn + col]       = v0;
            *(float2*)&C[(size_t)(row + 8) * Nn + col] = v1;
        }
    }
}

// ===========================================================================
// Conversion kernels (fp32 -> compensated bf16 split)
// ===========================================================================
__global__ __launch_bounds__(256)
void split_rows(const float* __restrict__ in, __nv_bfloat16* __restrict__ out, int M) {
    int idx = blockIdx.x * 256 + threadIdx.x;
    if (idx >= M * DD) return;
    int m = idx >> 10, k = idx & 1023;
    float x = in[idx];
    __nv_bfloat16 hi = __float2bfloat16(x);
    __nv_bfloat16 lo = __float2bfloat16(x - __bfloat162float(hi));
    __nv_bfloat16* o = out + (size_t)m * KP;
    o[k] = hi; o[DD + k] = lo; o[2 * DD + k] = hi;
}

__global__ __launch_bounds__(256)
void split_transpose(const float* __restrict__ W, __nv_bfloat16* __restrict__ out, int Nw) {
    __shared__ float t[32][33];
    int n0 = blockIdx.x * 32, k0 = blockIdx.y * 32;
    int tx = threadIdx.x, ty = threadIdx.y;  // 32 x 8
#pragma unroll
    for (int i = ty; i < 32; i += 8)
        t[i][tx] = W[(size_t)(k0 + i) * Nw + n0 + tx];
    __syncthreads();
#pragma unroll
    for (int i = ty; i < 32; i += 8) {
        int n = n0 + i, k = k0 + tx;
        float x = t[tx][i];
        __nv_bfloat16 hi = __float2bfloat16(x);
        __nv_bfloat16 lo = __float2bfloat16(x - __bfloat162float(hi));
        __nv_bfloat16* o = out + (size_t)n * KP;
        o[k] = hi; o[DD + k] = hi; o[2 * DD + k] = lo;
    }
}

// ===========================================================================
// Attention (anti-causal, softmax over j) — unchanged from R1 (passing)
// ===========================================================================
#define TILE 64
#define PAD  (TILE + 1)
#define SMEM_ATTN (4 * TILE * PAD * (int)sizeof(float))

__device__ __forceinline__ float rowmax16(float v) {
#pragma unroll
    for (int o = 8; o > 0; o >>= 1)
        v = fmaxf(v, __shfl_xor_sync(0xffffffffu, v, o, 16));
    return v;
}
__device__ __forceinline__ float rowsum16(float v) {
#pragma unroll
    for (int o = 8; o > 0; o >>= 1)
        v += __shfl_xor_sync(0xffffffffu, v, o, 16);
    return v;
}

__global__ __launch_bounds__(256, 3)
void attn_kernel(const float* __restrict__ qkv, float* __restrict__ outp) {
    extern __shared__ float sm[];
    float* Kt = sm;
    float* Qt = Kt + TILE * PAD;
    float* Vt = Qt + TILE * PAD;
    float* Pt = Vt + TILE * PAD;

    const int bh = blockIdx.y;
    const int b  = bh >> 4;
    const int h  = bh & 15;
    const int i0 = blockIdx.x * TILE;

    const int tid = threadIdx.x;
    const int ty  = tid >> 4;
    const int tx  = tid & 15;

    for (int idx = tid; idx < TILE * 16; idx += 256) {
        int r = idx >> 4;
        int c = (idx & 15) << 2;
        const float* src = qkv + ((size_t)(b * NN + i0 + r) * 3 * DD) + DD + h * EE + c;
        float4 v = *(const float4*)src;
        float* dst = &Kt[r * PAD + c];
        dst[0] = v.x; dst[1] = v.y; dst[2] = v.z; dst[3] = v.w;
    }

    float m[4], l[4], O[4][4];
#pragma unroll
    for (int r = 0; r < 4; r++) {
        m[r] = -INFINITY; l[r] = 0.0f;
#pragma unroll
        for (int c = 0; c < 4; c++) O[r][c] = 0.0f;
    }

    const int jt0 = i0 / TILE;
    const int nTiles = NN / TILE;

    for (int jt = jt0; jt < nTiles; jt++) {
        const int j0 = jt * TILE;
        for (int idx = tid; idx < TILE * 16; idx += 256) {
            int r = idx >> 4;
            int c = (idx & 15) << 2;
            const float* base = qkv + ((size_t)(b * NN + j0 + r) * 3 * DD) + h * EE + c;
            float4 qv = *(const float4*)(base);
            float4 vv = *(const float4*)(base + 2 * DD);
            float* qdst = &Qt[r * PAD + c];
            float* vdst = &Vt[r * PAD + c];
            qdst[0] = qv.x; qdst[1] = qv.y; qdst[2] = qv.z; qdst[3] = qv.w;
            vdst[0] = vv.x; vdst[1] = vv.y; vdst[2] = vv.z; vdst[3] = vv.w;
        }
        __syncthreads();

        float S[4][4];
#pragma unroll
        for (int r = 0; r < 4; r++)
#pragma unroll
            for (int c = 0; c < 4; c++) S[r][c] = 0.0f;

#pragma unroll 8
        for (int e = 0; e < EE; e++) {
            float kf[4], qf[4];
#pragma unroll
            for (int r = 0; r < 4; r++) kf[r] = Kt[(ty * 4 + r) * PAD + e];
#pragma unroll
            for (int c = 0; c < 4; c++) qf[c] = Qt[(tx * 4 + c) * PAD + e];
#pragma unroll
            for (int r = 0; r < 4; r++)
#pragma unroll
                for (int c = 0; c < 4; c++)
                    S[r][c] = fmaf(kf[r], qf[c], S[r][c]);
        }

        const bool diag = (j0 == i0);
#pragma unroll
        for (int r = 0; r < 4; r++) {
            int gi = i0 + ty * 4 + r;
#pragma unroll
            for (int c = 0; c < 4; c++) {
                int gj = j0 + tx * 4 + c;
                float sv = S[r][c] * 0.125f;
                if (diag && gj < gi) sv = -INFINITY;
                S[r][c] = sv;
            }
        }

        float scale[4];
#pragma unroll
        for (int r = 0; r < 4; r++) {
            float tmax = fmaxf(fmaxf(S[r][0], S[r][1]), fmaxf(S[r][2], S[r][3]));
            tmax = rowmax16(tmax);
            float mnew = fmaxf(m[r], tmax);
            scale[r] = __expf(m[r] - mnew);
            m[r] = mnew;
            float rs = 0.0f;
#pragma unroll
            for (int c = 0; c < 4; c++) {
                float p = __expf(S[r][c] - mnew);
                S[r][c] = p;
                rs += p;
            }
            rs = rowsum16(rs);
            l[r] = l[r] * scale[r] + rs;
#pragma unroll
            for (int c = 0; c < 4; c++) O[r][c] *= scale[r];
        }

#pragma unroll
        for (int r = 0; r < 4; r++)
#pragma unroll
            for (int c = 0; c < 4; c++)
                Pt[(ty * 4 + r) * PAD + (tx * 4 + c)] = S[r][c];
        __syncthreads();

#pragma unroll 8
        for (int j = 0; j < TILE; j++) {
            float vf[4];
#pragma unroll
            for (int c = 0; c < 4; c++) vf[c] = Vt[j * PAD + tx * 4 + c];
#pragma unroll
            for (int r = 0; r < 4; r++) {
                float p = Pt[(ty * 4 + r) * PAD + j];
#pragma unroll
                for (int c = 0; c < 4; c++)
                    O[r][c] = fmaf(p, vf[c], O[r][c]);
            }
        }
        __syncthreads();
    }

#pragma unroll
    for (int r = 0; r < 4; r++) {
        float inv = 1.0f / l[r];
        int gi = i0 + ty * 4 + r;
        float* dst = outp + (size_t)(b * NN + gi) * DD + h * EE + tx * 4;
        float4 v = make_float4(O[r][0] * inv, O[r][1] * inv, O[r][2] * inv, O[r][3] * inv);
        *(float4*)dst = v;
    }
}

// ===========================================================================
extern "C" void kernel_launch(void* const* d_in, const int* in_sizes, int n_in,
                              void* d_out, int out_size) {
    const float* x    = (const float*)d_in[0];
    const float* Wqkv = (const float*)d_in[1];
    const float* Wo   = (const float*)d_in[2];
    float* out = (float*)d_out;

    float* qkv = nullptr;  float* attn = nullptr;
    __nv_bfloat16* Abuf = nullptr;  __nv_bfloat16* Bbuf = nullptr;
    cudaGetSymbolAddress((void**)&qkv,  g_qkv);
    cudaGetSymbolAddress((void**)&attn, g_attn);
    cudaGetSymbolAddress((void**)&Abuf, g_A);
    cudaGetSymbolAddress((void**)&Bbuf, g_B);

    cudaFuncSetAttribute(gemm_hmma, cudaFuncAttributeMaxDynamicSharedMemorySize, SMEM_GEMM);
    cudaFuncSetAttribute(attn_kernel, cudaFuncAttributeMaxDynamicSharedMemorySize, SMEM_ATTN);

    // 1) x -> A' split
    split_rows<<<(MTOT * DD + 255) / 256, 256>>>(x, Abuf, MTOT);
    // 2) W_qkv -> B' split-transpose
    split_transpose<<<dim3(3 * DD / 32, DD / 32), dim3(32, 8)>>>(Wqkv, Bbuf, 3 * DD);
    // 3) QKV GEMM
    gemm_hmma<<<dim3(3 * DD / 128, MTOT / 128), 256, SMEM_GEMM>>>(Abuf, Bbuf, qkv, MTOT, 3 * DD);
    // 4) attention
    attn_kernel<<<dim3(NN / TILE, BB * HH), 256, SMEM_ATTN>>>(qkv, attn);
    // 5) attn out -> A' ; W_o -> B'
    split_rows<<<(MTOT * DD + 255) / 256, 256>>>(attn, Abuf, MTOT);
    split_transpose<<<dim3(DD / 32, DD / 32), dim3(32, 8)>>>(Wo, Bbuf, DD);
    // 6) O-proj GEMM
    gemm_hmma<<<dim3(DD / 128, MTOT / 128), 256, SMEM_GEMM>>>(Abuf, Bbuf, out, MTOT, DD);
}

// round 4
// speedup vs baseline: 2.3600x; 1.6737x over previous
#include <cuda_runtime.h>
#include <cuda_bf16.h>
#include <cstdint>
#include <math.h>

// ---------------------------------------------------------------------------
// Problem: x[4,2048,1024] f32; W_qkv[1024,3072]; W_o[1024,1024]; out[4,2048,1024]
//   1) split x -> A' bf16 [8192, 3072]  (hi | lo | hi along K)
//   2) split/transpose W_qkv -> B' bf16 [3072, 3072] (hi ; hi ; lo)
//   3) HMMA bf16 GEMM -> g_qkv f32 [8192, 3072]
//   4) tf32 mma flash-style anti-causal attention -> g_attn
//   5) split g_attn -> A' ; split/transpose W_o -> B'[1024,3072]
//   6) HMMA bf16 GEMM -> out
// ---------------------------------------------------------------------------
#define BB 4
#define NN 2048
#define DD 1024
#define HH 16
#define EE 64
#define MTOT (BB * NN)   // 8192
#define KP   3072
#define SA   40          // gemm smem row stride in bf16 (32 data + 8 pad)
#define NSTAGE 96        // KP / 32

__device__ float         g_qkv[MTOT * 3 * DD];
__device__ float         g_attn[MTOT * DD];
__device__ __nv_bfloat16 g_A[MTOT * KP];
__device__ __nv_bfloat16 g_B[3 * DD * KP];

// ===========================================================================
__device__ __forceinline__ uint32_t smem_u32(const void* p) {
    uint32_t a;
    asm("{ .reg .u64 t; cvta.to.shared.u64 t, %1; cvt.u32.u64 %0, t; }"
        : "=r"(a) : "l"(p));
    return a;
}
__device__ __forceinline__ void cp_async16(uint32_t dst, const void* src) {
    asm volatile("cp.async.cg.shared.global [%0], [%1], 16;"
                 :: "r"(dst), "l"(src) : "memory");
}
__device__ __forceinline__ void ldsm_x4(uint32_t* r, uint32_t addr) {
    asm volatile("ldmatrix.sync.aligned.m8n8.x4.shared.b16 {%0,%1,%2,%3}, [%4];"
                 : "=r"(r[0]), "=r"(r[1]), "=r"(r[2]), "=r"(r[3]) : "r"(addr));
}
__device__ __forceinline__ void mma_bf16(float* d, const uint32_t* a, const uint32_t* b) {
    asm volatile(
        "mma.sync.aligned.m16n8k16.row.col.f32.bf16.bf16.f32 "
        "{%0,%1,%2,%3}, {%4,%5,%6,%7}, {%8,%9}, {%0,%1,%2,%3};"
        : "+f"(d[0]), "+f"(d[1]), "+f"(d[2]), "+f"(d[3])
        : "r"(a[0]), "r"(a[1]), "r"(a[2]), "r"(a[3]), "r"(b[0]), "r"(b[1]));
}
__device__ __forceinline__ float tf32r(float x) {
    asm("cvt.rna.tf32.f32 %0, %0;" : "+f"(x));
    return x;
}
__device__ __forceinline__ void mma_tf32(float* d, const float* a, float b0f, float b1f) {
    uint32_t a0 = __float_as_uint(a[0]), a1 = __float_as_uint(a[1]);
    uint32_t a2 = __float_as_uint(a[2]), a3 = __float_as_uint(a[3]);
    uint32_t b0 = __float_as_uint(b0f), b1 = __float_as_uint(b1f);
    asm volatile(
        "mma.sync.aligned.m16n8k8.row.col.f32.tf32.tf32.f32 "
        "{%0,%1,%2,%3}, {%4,%5,%6,%7}, {%8,%9}, {%0,%1,%2,%3};"
        : "+f"(d[0]), "+f"(d[1]), "+f"(d[2]), "+f"(d[3])
        : "r"(a0), "r"(a1), "r"(a2), "r"(a3), "r"(b0), "r"(b1));
}

// ===========================================================================
// HMMA GEMM: C[M,Nn] f32 = A[M,KP] bf16 @ B[Nn,KP]^T bf16   (unchanged, R3)
// ===========================================================================
#define BUFB (128 * SA * 2)
#define SMEM_GEMM (3 * 2 * BUFB)

__global__ __launch_bounds__(256, 2)
void gemm_hmma(const __nv_bfloat16* __restrict__ A,
               const __nv_bfloat16* __restrict__ B,
               float* __restrict__ C, int M, int Nn) {
    extern __shared__ __nv_bfloat16 smbf[];
    const int tid  = threadIdx.x;
    const int wid  = tid >> 5;
    const int lane = tid & 31;
    const int m0 = blockIdx.y * 128;
    const int n0 = blockIdx.x * 128;
    const int wm = (wid >> 2) * 64;
    const int wn = (wid & 3) * 32;

    const uint32_t sbase = smem_u32(smbf);
    const uint32_t aoff0 = sbase;
    const uint32_t boff0 = sbase + 3 * BUFB;

    const __nv_bfloat16* Ag = A + (size_t)m0 * KP;
    const __nv_bfloat16* Bg = B + (size_t)n0 * KP;

    const int lr  = tid >> 1;
    const int lkc = (tid & 1) * 2;

    auto load_stage = [&](int s) {
        const int buf = s % 3;
        const uint32_t ab = aoff0 + buf * BUFB;
        const uint32_t bb = boff0 + buf * BUFB;
        const int k0 = s * 32;
#pragma unroll
        for (int j = 0; j < 2; j++) {
            const int kc = lkc + j;
            const uint32_t doff = (uint32_t)(lr * SA + kc * 8) * 2;
            cp_async16(ab + doff, Ag + (size_t)lr * KP + k0 + kc * 8);
            cp_async16(bb + doff, Bg + (size_t)lr * KP + k0 + kc * 8);
        }
        asm volatile("cp.async.commit_group;" ::: "memory");
    };

    float acc[4][4][4];
#pragma unroll
    for (int i = 0; i < 4; i++)
#pragma unroll
        for (int j = 0; j < 4; j++)
#pragma unroll
            for (int k = 0; k < 4; k++) acc[i][j][k] = 0.0f;

    const int arow  = wm + (lane & 15);
    const int akoff = (lane >> 4) * 8;
    const int brow  = wn + (lane >> 4) * 8 + (lane & 7);
    const int bkoff = ((lane >> 3) & 1) * 8;

    load_stage(0);
    load_stage(1);

    for (int s = 0; s < NSTAGE; s++) {
        if (s + 1 < NSTAGE)
            asm volatile("cp.async.wait_group 1;" ::: "memory");
        else
            asm volatile("cp.async.wait_group 0;" ::: "memory");
        __syncthreads();
        if (s + 2 < NSTAGE) load_stage(s + 2);

        const int buf = s % 3;
        const uint32_t ab = aoff0 + buf * BUFB;
        const uint32_t bb = boff0 + buf * BUFB;

#pragma unroll
        for (int ksub = 0; ksub < 2; ksub++) {
            uint32_t af[4][4], bf[2][4];
#pragma unroll
            for (int mt = 0; mt < 4; mt++)
                ldsm_x4(af[mt], ab + (uint32_t)((arow + mt * 16) * SA + ksub * 16 + akoff) * 2);
#pragma unroll
            for (int p = 0; p < 2; p++)
                ldsm_x4(bf[p], bb + (uint32_t)((brow + p * 16) * SA + ksub * 16 + bkoff) * 2);
#pragma unroll
            for (int mt = 0; mt < 4; mt++) {
#pragma unroll
                for (int nt = 0; nt < 4; nt++)
                    mma_bf16(acc[mt][nt], af[mt], &bf[nt >> 1][(nt & 1) * 2]);
            }
        }
    }

    const int grp = lane >> 2;
    const int tig = lane & 3;
#pragma unroll
    for (int mt = 0; mt < 4; mt++) {
#pragma unroll
        for (int nt = 0; nt < 4; nt++) {
            const int row = m0 + wm + mt * 16 + grp;
            const int col = n0 + wn + nt * 8 + tig * 2;
            float2 v0 = make_float2(acc[mt][nt][0], acc[mt][nt][1]);
            float2 v1 = make_float2(acc[mt][nt][2], acc[mt][nt][3]);
            *(float2*)&C[(size_t)row * Nn + col]       = v0;
            *(float2*)&C[(size_t)(row + 8) * Nn + col] = v1;
        }
    }
}

// ===========================================================================
// Conversion kernels (unchanged)
// ===========================================================================
__global__ __launch_bounds__(256)
void split_rows(const float* __restrict__ in, __nv_bfloat16* __restrict__ out, int M) {
    int idx = blockIdx.x * 256 + threadIdx.x;
    if (idx >= M * DD) return;
    int m = idx >> 10, k = idx & 1023;
    float x = in[idx];
    __nv_bfloat16 hi = __float2bfloat16(x);
    __nv_bfloat16 lo = __float2bfloat16(x - __bfloat162float(hi));
    __nv_bfloat16* o = out + (size_t)m * KP;
    o[k] = hi; o[DD + k] = lo; o[2 * DD + k] = hi;
}

__global__ __launch_bounds__(256)
void split_transpose(const float* __restrict__ W, __nv_bfloat16* __restrict__ out, int Nw) {
    __shared__ float t[32][33];
    int n0 = blockIdx.x * 32, k0 = blockIdx.y * 32;
    int tx = threadIdx.x, ty = threadIdx.y;
#pragma unroll
    for (int i = ty; i < 32; i += 8)
        t[i][tx] = W[(size_t)(k0 + i) * Nw + n0 + tx];
    __syncthreads();
#pragma unroll
    for (int i = ty; i < 32; i += 8) {
        int n = n0 + i, k = k0 + tx;
        float x = t[tx][i];
        __nv_bfloat16 hi = __float2bfloat16(x);
        __nv_bfloat16 lo = __float2bfloat16(x - __bfloat162float(hi));
        __nv_bfloat16* o = out + (size_t)n * KP;
        o[k] = hi; o[DD + k] = hi; o[2 * DD + k] = lo;
    }
}

// ===========================================================================
// Attention with tf32 mma (anti-causal: row i attends j >= i, softmax over j)
// CTA: 128 K-rows (i) x one (b,h). 8 warps, warp w owns rows [16w, 16w+16).
// Streams 64-wide j-tiles from the diagonal. P stays in registers
// (C-frag -> A-frag via shuffles). V stored e-major for conflict-free B loads.
// ===========================================================================
#define AT_I 128
#define AT_J 64
#define STRD 68
#define SMEM_ATTN ((AT_I + AT_J + AT_J) * STRD * (int)sizeof(float))

__global__ __launch_bounds__(256, 2)
void attn_tc(const float* __restrict__ qkv, float* __restrict__ outp) {
    extern __shared__ float sm[];
    float* Ksm = sm;                       // [128][STRD]  rows i, cols e
    float* Qsm = sm + AT_I * STRD;         // [64][STRD]   rows j, cols e
    float* Vsm = sm + (AT_I + AT_J) * STRD;// [64][STRD]   rows e, cols j

    const int it = blockIdx.x;
    const int bh = blockIdx.y;
    const int b = bh >> 4, h = bh & 15;
    const int i0 = it * AT_I;

    const int tid  = threadIdx.x;
    const int wid  = tid >> 5;
    const int lane = tid & 31;
    const int g = lane >> 2;     // group id (0..7)
    const int t = lane & 3;      // thread-in-group
    const int wm = wid * 16;     // warp row offset within i-tile

    const size_t RS = 3 * DD;    // qkv row stride
    const float* Qg = qkv + h * EE;
    const float* Kg = qkv + DD + h * EE;
    const float* Vg = qkv + 2 * DD + h * EE;

    // ---- load K tile once: rows i0..i0+127 ----
#pragma unroll
    for (int q = 0; q < 8; q++) {
        int idx = q * 256 + tid;            // 2048 float4 chunks
        int r = idx >> 4, ec = (idx & 15) << 2;
        float4 v = *(const float4*)(Kg + (size_t)(b * NN + i0 + r) * RS + ec);
        float* d = Ksm + r * STRD + ec;
        d[0] = tf32r(v.x); d[1] = tf32r(v.y); d[2] = tf32r(v.z); d[3] = tf32r(v.w);
    }

    float m0 = -1e30f, m1 = -1e30f, l0 = 0.0f, l1 = 0.0f;
    float O[8][4];
#pragma unroll
    for (int nt = 0; nt < 8; nt++)
#pragma unroll
        for (int k = 0; k < 4; k++) O[nt][k] = 0.0f;

    const int r0g = i0 + wm + g;     // global row of this thread's row 0
    const int r1g = r0g + 8;

    const int jt0 = it * 2;
    const int nJT = NN / AT_J;

    for (int jt = jt0; jt < nJT; jt++) {
        const int j0 = jt * AT_J;
        __syncthreads();   // previous iteration finished reading Qsm/Vsm (and Ksm written)

        // ---- load Q tile (rows j0..j0+63) ----
#pragma unroll
        for (int q = 0; q < 4; q++) {
            int idx = q * 256 + tid;        // 1024 chunks
            int r = idx >> 4, ec = (idx & 15) << 2;
            float4 v = *(const float4*)(Qg + (size_t)(b * NN + j0 + r) * RS + ec);
            float* d = Qsm + r * STRD + ec;
            d[0] = tf32r(v.x); d[1] = tf32r(v.y); d[2] = tf32r(v.z); d[3] = tf32r(v.w);
        }
        // ---- load V tile transposed: Vsm[e][j] ----
#pragma unroll
        for (int q = 0; q < 4; q++) {
            int ec = (wid * 2 + (q >> 1)) << 2;   // e chunk base (0..60 step 4)
            int j  = ((q & 1) << 5) + lane;       // 0..63
            float4 v = *(const float4*)(Vg + (size_t)(b * NN + j0 + j) * RS + ec);
            Vsm[(ec + 0) * STRD + j] = tf32r(v.x);
            Vsm[(ec + 1) * STRD + j] = tf32r(v.y);
            Vsm[(ec + 2) * STRD + j] = tf32r(v.z);
            Vsm[(ec + 3) * STRD + j] = tf32r(v.w);
        }
        __syncthreads();

        // ---- S = K_i . Q_j  (m=i warp 16, n=j 64, k=e 64) ----
        float C[8][4];
#pragma unroll
        for (int nt = 0; nt < 8; nt++)
#pragma unroll
            for (int k = 0; k < 4; k++) C[nt][k] = 0.0f;

#pragma unroll
        for (int kt = 0; kt < 8; kt++) {
            float a[4];
            a[0] = Ksm[(wm + g)     * STRD + kt * 8 + t];
            a[1] = Ksm[(wm + g + 8) * STRD + kt * 8 + t];
            a[2] = Ksm[(wm + g)     * STRD + kt * 8 + t + 4];
            a[3] = Ksm[(wm + g + 8) * STRD + kt * 8 + t + 4];
#pragma unroll
            for (int nt = 0; nt < 8; nt++) {
                float b0 = Qsm[(nt * 8 + g) * STRD + kt * 8 + t];
                float b1 = Qsm[(nt * 8 + g) * STRD + kt * 8 + t + 4];
                mma_tf32(C[nt], a, b0, b1);
            }
        }

        // ---- scale + mask ----
        const bool needmask = (j0 < i0 + AT_I);
        float rmax0 = -1e30f, rmax1 = -1e30f;
#pragma unroll
        for (int nt = 0; nt < 8; nt++) {
            C[nt][0] *= 0.125f; C[nt][1] *= 0.125f;
            C[nt][2] *= 0.125f; C[nt][3] *= 0.125f;
            if (needmask) {
                int c0 = j0 + nt * 8 + 2 * t;
                int c1 = c0 + 1;
                if (c0 < r0g) C[nt][0] = -1e30f;
                if (c1 < r0g) C[nt][1] = -1e30f;
                if (c0 < r1g) C[nt][2] = -1e30f;
                if (c1 < r1g) C[nt][3] = -1e30f;
            }
            rmax0 = fmaxf(rmax0, fmaxf(C[nt][0], C[nt][1]));
            rmax1 = fmaxf(rmax1, fmaxf(C[nt][2], C[nt][3]));
        }
        rmax0 = fmaxf(rmax0, __shfl_xor_sync(0xffffffffu, rmax0, 1));
        rmax0 = fmaxf(rmax0, __shfl_xor_sync(0xffffffffu, rmax0, 2));
        rmax1 = fmaxf(rmax1, __shfl_xor_sync(0xffffffffu, rmax1, 1));
        rmax1 = fmaxf(rmax1, __shfl_xor_sync(0xffffffffu, rmax1, 2));

        float mn0 = fmaxf(m0, rmax0), mn1 = fmaxf(m1, rmax1);
        float sc0 = __expf(m0 - mn0), sc1 = __expf(m1 - mn1);
        m0 = mn0; m1 = mn1;

        float rs0 = 0.0f, rs1 = 0.0f;
#pragma unroll
        for (int nt = 0; nt < 8; nt++) {
            C[nt][0] = __expf(C[nt][0] - mn0);
            C[nt][1] = __expf(C[nt][1] - mn0);
            C[nt][2] = __expf(C[nt][2] - mn1);
            C[nt][3] = __expf(C[nt][3] - mn1);
            rs0 += C[nt][0] + C[nt][1];
            rs1 += C[nt][2] + C[nt][3];
        }
        rs0 += __shfl_xor_sync(0xffffffffu, rs0, 1);
        rs0 += __shfl_xor_sync(0xffffffffu, rs0, 2);
        rs1 += __shfl_xor_sync(0xffffffffu, rs1, 1);
        rs1 += __shfl_xor_sync(0xffffffffu, rs1, 2);
        l0 = l0 * sc0 + rs0;
        l1 = l1 * sc1 + rs1;
#pragma unroll
        for (int nt = 0; nt < 8; nt++) {
            O[nt][0] *= sc0; O[nt][1] *= sc0;
            O[nt][2] *= sc1; O[nt][3] *= sc1;
        }

        // ---- O += P @ V  (k=j 64, n=e 64); P fragments built via shuffles ----
        const uint32_t srcA = (lane & 28) | (t >> 1);
        const uint32_t srcB = srcA + 2;
#pragma unroll
        for (int kt = 0; kt < 8; kt++) {
            float p0a = __shfl_sync(0xffffffffu, C[kt][0], srcA);
            float p1a = __shfl_sync(0xffffffffu, C[kt][1], srcA);
            float p2a = __shfl_sync(0xffffffffu, C[kt][2], srcA);
            float p3a = __shfl_sync(0xffffffffu, C[kt][3], srcA);
            float p0b = __shfl_sync(0xffffffffu, C[kt][0], srcB);
            float p1b = __shfl_sync(0xffffffffu, C[kt][1], srcB);
            float p2b = __shfl_sync(0xffffffffu, C[kt][2], srcB);
            float p3b = __shfl_sync(0xffffffffu, C[kt][3], srcB);
            float a[4];
            a[0] = tf32r((t & 1) ? p1a : p0a);   // (row g,   col t)
            a[1] = tf32r((t & 1) ? p3a : p2a);   // (row g+8, col t)
            a[2] = tf32r((t & 1) ? p1b : p0b);   // (row g,   col t+4)
            a[3] = tf32r((t & 1) ? p3b : p2b);   // (row g+8, col t+4)
#pragma unroll
            for (int nt = 0; nt < 8; nt++) {
                float b0 = Vsm[(nt * 8 + g) * STRD + kt * 8 + t];
                float b1 = Vsm[(nt * 8 + g) * STRD + kt * 8 + t + 4];
                mma_tf32(O[nt], a, b0, b1);
            }
        }
    }

    // ---- normalize + store ----
    float inv0 = 1.0f / l0, inv1 = 1.0f / l1;
    float* out0 = outp + (size_t)(b * NN + r0g) * DD + h * EE;
    float* out1 = outp + (size_t)(b * NN + r1g) * DD + h * EE;
#pragma unroll
    for (int nt = 0; nt < 8; nt++) {
        int col = nt * 8 + 2 * t;
        *(float2*)(out0 + col) = make_float2(O[nt][0] * inv0, O[nt][1] * inv0);
        *(float2*)(out1 + col) = make_float2(O[nt][2] * inv1, O[nt][3] * inv1);
    }
}

// ===========================================================================
extern "C" void kernel_launch(void* const* d_in, const int* in_sizes, int n_in,
                              void* d_out, int out_size) {
    const float* x    = (const float*)d_in[0];
    const float* Wqkv = (const float*)d_in[1];
    const float* Wo   = (const float*)d_in[2];
    float* out = (float*)d_out;

    float* qkv = nullptr;  float* attn = nullptr;
    __nv_bfloat16* Abuf = nullptr;  __nv_bfloat16* Bbuf = nullptr;
    cudaGetSymbolAddress((void**)&qkv,  g_qkv);
    cudaGetSymbolAddress((void**)&attn, g_attn);
    cudaGetSymbolAddress((void**)&Abuf, g_A);
    cudaGetSymbolAddress((void**)&Bbuf, g_B);

    cudaFuncSetAttribute(gemm_hmma, cudaFuncAttributeMaxDynamicSharedMemorySize, SMEM_GEMM);
    cudaFuncSetAttribute(attn_tc, cudaFuncAttributeMaxDynamicSharedMemorySize, SMEM_ATTN);

    // 1) x -> A' split
    split_rows<<<(MTOT * DD + 255) / 256, 256>>>(x, Abuf, MTOT);
    // 2) W_qkv -> B' split-transpose
    split_transpose<<<dim3(3 * DD / 32, DD / 32), dim3(32, 8)>>>(Wqkv, Bbuf, 3 * DD);
    // 3) QKV GEMM
    gemm_hmma<<<dim3(3 * DD / 128, MTOT / 128), 256, SMEM_GEMM>>>(Abuf, Bbuf, qkv, MTOT, 3 * DD);
    // 4) attention (tf32 tensor cores)
    attn_tc<<<dim3(NN / AT_I, BB * HH), 256, SMEM_ATTN>>>(qkv, attn);
    // 5) attn out -> A' ; W_o -> B'
    split_rows<<<(MTOT * DD + 255) / 256, 256>>>(attn, Abuf, MTOT);
    split_transpose<<<dim3(DD / 32, DD / 32), dim3(32, 8)>>>(Wo, Bbuf, DD);
    // 6) O-proj GEMM
    gemm_hmma<<<dim3(DD / 128, MTOT / 128), 256, SMEM_GEMM>>>(Abuf, Bbuf, out, MTOT, DD);
}